// round 2
// baseline (speedup 1.0000x reference)
#include <cuda_runtime.h>
#include <math.h>

// ---------------- model constants ----------------
constexpr int Dm  = 768;
constexpr int DIm = 1536;
constexpr int Nst = 16;
constexpr int Rr  = 48;
constexpr int NLs = 8;
constexpr int Bb  = 2;
constexpr int Ll  = 1024;
constexpr int Mrows = Bb * Ll;          // 2048
constexpr float EPSf = 1e-5f;

// ---------------- scratch (static device memory; no allocations) ----------------
constexpr size_t OFF_RES = 0;
constexpr size_t OFF_H   = OFF_RES + (size_t)Mrows * Dm;
constexpr size_t OFF_X   = OFF_H   + (size_t)Mrows * Dm;
constexpr size_t OFF_XZ  = OFF_X   + (size_t)Mrows * Dm;
constexpr size_t OFF_XC  = OFF_XZ  + (size_t)Mrows * 2 * DIm;
constexpr size_t OFF_DT  = OFF_XC  + (size_t)Mrows * DIm;
constexpr size_t OFF_Y   = OFF_DT  + (size_t)Mrows * DIm;
constexpr size_t OFF_DBL = OFF_Y   + (size_t)Mrows * DIm;
constexpr size_t SCRATCH_TOTAL = OFF_DBL + (size_t)Mrows * 80;

__device__ float g_scratch[SCRATCH_TOTAL];

// ---------------- embedding gather ----------------
__global__ void embed_kernel(const int* __restrict__ ids,
                             const float* __restrict__ emb,
                             float* __restrict__ res)
{
    int idx = blockIdx.x * blockDim.x + threadIdx.x;
    if (idx >= Mrows * Dm) return;
    int row = idx / Dm;
    int c   = idx - row * Dm;
    res[idx] = emb[(size_t)ids[row] * Dm + c];
}

// ---------------- residual add + RMSNorm ----------------
// res[row] (+= xadd[row] if addx), out[row] = res * rsqrt(mean(res^2)+eps) * w
__global__ void rms_resid_kernel(float* __restrict__ res,
                                 const float* __restrict__ xadd,
                                 const float* __restrict__ w,
                                 float* __restrict__ out,
                                 int addx)
{
    const int row = blockIdx.x;
    const int tid = threadIdx.x;          // 256 threads, D=768 -> 3 elems each
    float v[3];
    float local = 0.f;
#pragma unroll
    for (int j = 0; j < 3; j++) {
        int c = tid + j * 256;
        float t = res[(size_t)row * Dm + c];
        if (addx) {
            t += xadd[(size_t)row * Dm + c];
            res[(size_t)row * Dm + c] = t;
        }
        v[j] = t;
        local += t * t;
    }
#pragma unroll
    for (int o = 16; o > 0; o >>= 1) local += __shfl_xor_sync(0xffffffffu, local, o);
    __shared__ float warpsum[8];
    __shared__ float sscale;
    if ((tid & 31) == 0) warpsum[tid >> 5] = local;
    __syncthreads();
    if (tid == 0) {
        float t = 0.f;
#pragma unroll
        for (int j = 0; j < 8; j++) t += warpsum[j];
        sscale = rsqrtf(t / (float)Dm + EPSf);
    }
    __syncthreads();
    float sc = sscale;
#pragma unroll
    for (int j = 0; j < 3; j++) {
        int c = tid + j * 256;
        out[(size_t)row * Dm + c] = v[j] * sc * w[c];
    }
}

// ---------------- generic GEMM: C[M,N] = A[M,K](lda) * W[N,K]^T ----------------
// EPI 0: plain   EPI 1: softplus(acc + bias[n])
template <int EPI>
__global__ void gemm_atb(const float* __restrict__ A, int lda,
                         const float* __restrict__ W,
                         float* __restrict__ C, int ldc,
                         int M, int N, int K,
                         const float* __restrict__ bias)
{
    __shared__ float As[16][68];
    __shared__ float Ws[16][68];
    const int bm = blockIdx.y * 64;
    const int bn = blockIdx.x * 64;
    const int tid = threadIdx.x;
    const int r0 = (tid >> 4) << 2;
    const int c0 = (tid & 15) << 2;
    float acc[4][4] = {};

    for (int k0 = 0; k0 < K; k0 += 16) {
#pragma unroll
        for (int i = 0; i < 4; i++) {
            int idx = tid + i * 256;
            int m = idx >> 4, k = idx & 15;
            int gm = bm + m;
            As[k][m] = (gm < M) ? A[(size_t)gm * lda + k0 + k] : 0.f;
            int gn = bn + m;
            Ws[k][m] = (gn < N) ? W[(size_t)gn * K + k0 + k] : 0.f;
        }
        __syncthreads();
#pragma unroll
        for (int k = 0; k < 16; k++) {
            float a0 = As[k][r0 + 0], a1 = As[k][r0 + 1], a2 = As[k][r0 + 2], a3 = As[k][r0 + 3];
            float b0 = Ws[k][c0 + 0], b1 = Ws[k][c0 + 1], b2 = Ws[k][c0 + 2], b3 = Ws[k][c0 + 3];
            acc[0][0] += a0 * b0; acc[0][1] += a0 * b1; acc[0][2] += a0 * b2; acc[0][3] += a0 * b3;
            acc[1][0] += a1 * b0; acc[1][1] += a1 * b1; acc[1][2] += a1 * b2; acc[1][3] += a1 * b3;
            acc[2][0] += a2 * b0; acc[2][1] += a2 * b1; acc[2][2] += a2 * b2; acc[2][3] += a2 * b3;
            acc[3][0] += a3 * b0; acc[3][1] += a3 * b1; acc[3][2] += a3 * b2; acc[3][3] += a3 * b3;
        }
        __syncthreads();
    }

#pragma unroll
    for (int i = 0; i < 4; i++) {
        int gm = bm + r0 + i;
        if (gm >= M) continue;
#pragma unroll
        for (int j = 0; j < 4; j++) {
            int gn = bn + c0 + j;
            if (gn >= N) continue;
            float v = acc[i][j];
            if (EPI == 1) {
                v += bias[gn];
                v = (v > 20.f) ? v : log1pf(expf(v));  // softplus
            }
            C[(size_t)gm * ldc + gn] = v;
        }
    }
}

// ---------------- depthwise causal conv (K=4) + SiLU ----------------
__global__ void conv_silu_kernel(const float* __restrict__ xz,
                                 const float* __restrict__ w,
                                 const float* __restrict__ bias,
                                 float* __restrict__ xc)
{
    int idx = blockIdx.x * blockDim.x + threadIdx.x;
    if (idx >= Mrows * DIm) return;
    int row = idx / DIm;          // b*L + l
    int c   = idx - row * DIm;
    int l   = row & (Ll - 1);
    float s = bias[c];
#pragma unroll
    for (int k = 0; k < 4; k++) {
        int ll = l - 3 + k;
        if (ll >= 0) s += w[c * 4 + k] * xz[(size_t)(row - 3 + k) * (2 * DIm) + c];
    }
    xc[idx] = s / (1.f + expf(-s));   // silu
}

// ---------------- selective scan + skip + SiLU gate ----------------
// one thread per (b, d); N=16 states in registers
__global__ void scan_kernel(const float* __restrict__ xc,
                            const float* __restrict__ dt,
                            const float* __restrict__ dbl,
                            const float* __restrict__ A_log,
                            const float* __restrict__ Dp,
                            const float* __restrict__ xz,
                            float* __restrict__ y)
{
    int d = blockIdx.x * blockDim.x + threadIdx.x;
    int b = blockIdx.y;
    if (d >= DIm) return;
    float Ac[16], st[16];
#pragma unroll
    for (int n = 0; n < 16; n++) {
        Ac[n] = -expf(A_log[(size_t)d * 16 + n]);
        st[n] = 0.f;
    }
    float dp = Dp[d];
    for (int l = 0; l < Ll; l++) {
        size_t row = (size_t)b * Ll + l;
        float u   = xc[row * DIm + d];
        float dtt = dt[row * DIm + d];
        const float* bl = dbl + row * 80;
        float du = dtt * u;
        float yv = 0.f;
#pragma unroll
        for (int n = 0; n < 16; n++) {
            float e = __expf(dtt * Ac[n]);
            st[n] = e * st[n] + du * bl[48 + n];
            yv += st[n] * bl[64 + n];
        }
        yv += u * dp;
        float z = xz[row * (2 * DIm) + DIm + d];
        yv *= z / (1.f + __expf(-z));     // * silu(z)
        y[row * DIm + d] = yv;
    }
}

// ---------------- host launcher ----------------
extern "C" void kernel_launch(void* const* d_in, const int* in_sizes, int n_in,
                              void* d_out, int out_size)
{
    const int*   ids       = (const int*)  d_in[0];
    const float* emb       = (const float*)d_in[1];
    const float* in_proj_w = (const float*)d_in[2];   // [NL, 2*DI, D]
    const float* conv_w    = (const float*)d_in[3];   // [NL, DI, 4]
    const float* conv_b    = (const float*)d_in[4];   // [NL, DI]
    const float* x_proj_w  = (const float*)d_in[5];   // [NL, 80, DI]
    const float* dt_proj_w = (const float*)d_in[6];   // [NL, DI, 48]
    const float* dt_proj_b = (const float*)d_in[7];   // [NL, DI]
    const float* A_log     = (const float*)d_in[8];   // [NL, DI, 16]
    const float* D_param   = (const float*)d_in[9];   // [NL, DI]
    const float* out_proj_w= (const float*)d_in[10];  // [NL, D, DI]
    const float* norm_w    = (const float*)d_in[11];  // [NL, D]
    const float* norm_f_w  = (const float*)d_in[12];  // [D]
    float* out = (float*)d_out;

    float* s = nullptr;
    cudaGetSymbolAddress((void**)&s, g_scratch);
    float* res = s + OFF_RES;
    float* h   = s + OFF_H;
    float* x   = s + OFF_X;
    float* xz  = s + OFF_XZ;
    float* xc  = s + OFF_XC;
    float* dt  = s + OFF_DT;
    float* y   = s + OFF_Y;
    float* dbl = s + OFF_DBL;

    embed_kernel<<<(Mrows * Dm + 255) / 256, 256>>>(ids, emb, res);

    for (int i = 0; i < NLs; i++) {
        // h = rms(res += x)
        rms_resid_kernel<<<Mrows, 256>>>(res, x, norm_w + (size_t)i * Dm, h, i > 0);

        // xz = h @ in_proj^T   [2048,3072]
        {
            dim3 g((2 * DIm + 63) / 64, (Mrows + 63) / 64);
            gemm_atb<0><<<g, 256>>>(h, Dm, in_proj_w + (size_t)i * 2 * DIm * Dm,
                                    xz, 2 * DIm, Mrows, 2 * DIm, Dm, nullptr);
        }

        // xc = silu(causal depthwise conv(xi) + b)
        conv_silu_kernel<<<(Mrows * DIm + 255) / 256, 256>>>(
            xz, conv_w + (size_t)i * DIm * 4, conv_b + (size_t)i * DIm, xc);

        // dbl = xc @ x_proj^T   [2048,80]
        {
            dim3 g((80 + 63) / 64, (Mrows + 63) / 64);
            gemm_atb<0><<<g, 256>>>(xc, DIm, x_proj_w + (size_t)i * 80 * DIm,
                                    dbl, 80, Mrows, 80, DIm, nullptr);
        }

        // dt = softplus(dbl[:, :48] @ dt_proj^T + dt_bias)   [2048,1536]
        {
            dim3 g((DIm + 63) / 64, (Mrows + 63) / 64);
            gemm_atb<1><<<g, 256>>>(dbl, 80, dt_proj_w + (size_t)i * DIm * Rr,
                                    dt, DIm, Mrows, DIm, Rr,
                                    dt_proj_b + (size_t)i * DIm);
        }

        // selective scan + D skip + silu(z) gate
        {
            dim3 g(DIm / 128, Bb);
            scan_kernel<<<g, 128>>>(xc, dt, dbl,
                                    A_log + (size_t)i * DIm * Nst,
                                    D_param + (size_t)i * DIm, xz, y);
        }

        // x = y @ out_proj^T   [2048,768]
        {
            dim3 g((Dm + 63) / 64, (Mrows + 63) / 64);
            gemm_atb<0><<<g, 256>>>(y, DIm, out_proj_w + (size_t)i * Dm * DIm,
                                    x, Dm, Mrows, Dm, DIm, nullptr);
        }
    }

    // final: out = rms(res + x) * norm_f_w
    rms_resid_kernel<<<Mrows, 256>>>(res, x, norm_f_w, out, 1);
}